// round 7
// baseline (speedup 1.0000x reference)
#include <cuda_runtime.h>
#include <stdint.h>

#define REP      640
#define ROWS     16
#define NBIN     64
#define MAXM     32768
#define MAXSTEPS (MAXM + NBIN + 4)

// -------- device-global scratch --------
__device__ unsigned char g_flag[MAXM];
__device__ unsigned g_ta[MAXM];
__device__ unsigned g_tc[MAXM];
__device__ unsigned g_tz[MAXM];
__device__ int      g_tb[MAXM];
__device__ int      g_tp[MAXM];
__device__ __align__(16) uint4 g_prog[MAXSTEPS];
__device__ int g_nsteps;
__device__ int g_split;
__device__ int g_irregular;

// ---- prep: detect runs -> 32-wide steps -> bin by output block -> program ----
__global__ void k_prep(const void* __restrict__ r1, const void* __restrict__ r2,
                       const void* __restrict__ ro, const float* __restrict__ cg,
                       int M, int out_dim) {
    __shared__ int s_sc[1024];
    __shared__ int s_carry;
    __shared__ int scnt[NBIN];
    __shared__ int sdum[NBIN];
    __shared__ int srp[NBIN + 1];
    __shared__ unsigned s_or;
    __shared__ int s_ns;
    int t = threadIdx.x;
    const unsigned* cgu = (const unsigned*)cg;

    for (int i = t; i < NBIN; i += 1024) { scnt[i] = 0; sdum[i] = 0; }
    if (t == 0) { s_or = 0u; s_carry = -1; s_ns = 0; g_irregular = 0; }
    __syncthreads();

    // int64 detection: odd 32-bit words of ro all zero -> int64
    {
        const unsigned* rr = (const unsigned*)ro;
        int lim = (M < 4096) ? M : 4096;
        unsigned v = 0;
        for (int i = 1 + 2 * t; i < lim; i += 2048) v |= rr[i];
        if (v) s_or = 1u;                       // benign race, same value
    }
    __syncthreads();
    int is64 = (s_or == 0u);
#define GETI(p, i) (is64 ? (int)((const long long*)(p))[i] : ((const int*)(p))[i])

    // pass A: run-break flags
    for (int i = t; i < M; i += 1024) {
        int rb;
        if (i == 0) rb = 1;
        else rb = !((GETI(r1, i) == GETI(r1, i - 1) + 1) &&
                    (GETI(r2, i) == GETI(r2, i - 1) + 1) &&
                    (GETI(ro, i) == GETI(ro, i - 1) + 1) &&
                    (cgu[i] == cgu[i - 1]));
        g_flag[i] = (unsigned char)rb;
    }
    __syncthreads();

    // pass B: chunked max-scan for run starts; emit 32-wide steps
    for (int base = 0; base < M; base += 1024) {
        int i = base + t;
        int rb = (i < M) ? (int)g_flag[i] : 0;
        s_sc[t] = rb ? i : -1;
        __syncthreads();
        for (int off = 1; off < 1024; off <<= 1) {
            int v = (t >= off) ? s_sc[t - off] : -1;
            __syncthreads();
            if (v > s_sc[t]) s_sc[t] = v;
            __syncthreads();
        }
        int rstart = (s_sc[t] > s_carry) ? s_sc[t] : s_carry;
        if (i < M && ((i - rstart) & 31) == 0) {
            int wdt = 32;
            for (int k = 1; k < 32; ++k)
                if (i + k >= M || g_flag[i + k]) { wdt = k; break; }
            int a = GETI(r1, i), b = GETI(r2, i), o = GETI(ro, i);
            int bin = o >> 5;
            if (bin >= NBIN) { bin = NBIN - 1; g_irregular = 1; }
            if ((o & 31) || (wdt < 32)) g_irregular = 1;
            int sidx = atomicAdd(&s_ns, 1);
            g_ta[sidx] = (unsigned)a | ((unsigned)b << 16);
            g_tc[sidx] = cgu[i];
            g_tz[sidx] = (unsigned)o | ((unsigned)wdt << 16);
            g_tb[sidx] = bin;
            g_tp[sidx] = atomicAdd(&scnt[bin], 1);
        }
        __syncthreads();
        if (t == 0 && s_sc[1023] > s_carry) s_carry = s_sc[1023];
        __syncthreads();
    }

    // empty-bin dummies (zero-fill their output block via flush of acc=0)
    int nblk = (out_dim + 31) >> 5;
    if (nblk > NBIN) nblk = NBIN;
    if (t < nblk && scnt[t] == 0) { scnt[t] = 1; sdum[t] = 1; }
    __syncthreads();

    if (t == 0) {
        int acc = 0;
        for (int b = 0; b < NBIN; ++b) { srp[b] = acc; acc += scnt[b]; }
        srp[NBIN] = acc;
        g_nsteps = acc;
        int half = acc >> 1, best = 0, bd = acc + 1;
        for (int b = 0; b <= NBIN; ++b) {
            int d = srp[b] - half; if (d < 0) d = -d;
            if (d < bd) { bd = d; best = srp[b]; }
        }
        g_split = best;
    }
    __syncthreads();

    // scatter steps into binned program
    int ns = s_ns;
    for (int s = t; s < ns; s += 1024) {
        int slot = srp[g_tb[s]] + g_tp[s];
        g_prog[slot] = make_uint4(g_ta[s], g_tc[s], g_tz[s], 0u);
    }
    if (t < nblk && sdum[t])
        g_prog[srp[t]] = make_uint4(0u, 0u, (unsigned)(t << 5) | (32u << 16), 0u);
    __syncthreads();

    // flush flag on last slot of each nonempty bin
    if (t < NBIN && scnt[t] > 0) g_prog[srp[t + 1] - 1].w = 1u;
#undef GETI
}

// ---- main: warp = batch row (16 rows/CTA, 2 warps/row split the program) ----
__global__ __launch_bounds__(1024, 2)
void k_main(const float* __restrict__ x1, const float* __restrict__ x2,
            float* __restrict__ out, int N, int out_dim) {
    extern __shared__ float sm[];
    float* xs1 = sm;                 // [ROWS][REP] row-major
    float* xs2 = sm + ROWS * REP;

    int tid  = threadIdx.x;
    int lane = tid & 31;
    int w    = tid >> 5;
    int row  = w & 15;
    int half = w >> 4;
    int rowbase = blockIdx.x * ROWS;

    // prologue: straight float4 copy, no transpose
    if (rowbase + ROWS <= N) {
        const float4* p1 = (const float4*)(x1 + (size_t)rowbase * REP);
        const float4* p2 = (const float4*)(x2 + (size_t)rowbase * REP);
        float4* s1 = (float4*)xs1;
        float4* s2 = (float4*)xs2;
#pragma unroll
        for (int k = 0; k < 3; ++k) {
            int i = tid + k * 1024;
            if (i < ROWS * REP / 4) { s1[i] = p1[i]; s2[i] = p2[i]; }
        }
    } else {
        for (int i = tid; i < ROWS * REP; i += 1024) {
            int gr = rowbase + i / REP;
            xs1[i] = (gr < N) ? x1[(size_t)gr * REP + (i % REP)] : 0.f;
            xs2[i] = (gr < N) ? x2[(size_t)gr * REP + (i % REP)] : 0.f;
        }
    }
    __syncthreads();

    int gr = rowbase + row;
    if (gr >= N) return;

    int S     = g_nsteps;
    int split = g_split;
    int lo = half ? split : 0;
    int hi = half ? S     : split;
    const float* r1p = xs1 + row * REP + lane;
    const float* r2p = xs2 + row * REP + lane;
    float* orow = out + (size_t)gr * out_dim;

    float acc = 0.f;
    if (!g_irregular) {
#pragma unroll 4
        for (int s = lo; s < hi; ++s) {
            uint4 st = g_prog[s];                    // warp-uniform, L1-hot
            float va = r1p[st.x & 0xffffu];
            float vb = r2p[st.x >> 16];
            acc = fmaf(__uint_as_float(st.y) * va, vb, acc);
            if (st.w) {
                orow[(st.z & 0xffffu) + lane] = acc;
                acc = 0.f;
            }
        }
    } else {
        for (int s = lo; s < hi; ++s) {
            uint4 st = g_prog[s];
            float va = r1p[st.x & 0xffffu];
            float vb = r2p[st.x >> 16];
            float c  = ((unsigned)lane < (st.z >> 16)) ? __uint_as_float(st.y) : 0.f;
            acc = fmaf(c * va, vb, acc);
            if (st.w) {
                orow[(st.z & 0xffffu) + lane] = acc;
                acc = 0.f;
            }
        }
    }
}

// -------- launcher --------
extern "C" void kernel_launch(void* const* d_in, const int* in_sizes, int n_in,
                              void* d_out, int out_size) {
    const float* x1 = (const float*)d_in[0];
    const float* x2 = (const float*)d_in[1];
    const float* cg = (const float*)d_in[2];
    const void*  r1 = d_in[3];
    const void*  r2 = d_in[4];
    const void*  ro = d_in[5];

    int M = in_sizes[2];
    if (M > MAXM) M = MAXM;
    int N = in_sizes[0] / REP;
    int out_dim = out_size / N;

    k_prep<<<1, 1024>>>(r1, r2, ro, cg, M, out_dim);

    int smem = 2 * ROWS * REP * (int)sizeof(float);   // 81920
    cudaFuncSetAttribute(k_main, cudaFuncAttributeMaxDynamicSharedMemorySize, smem);
    k_main<<<(N + ROWS - 1) / ROWS, 1024, smem>>>(x1, x2, (float*)d_out, N, out_dim);
}

// round 8
// speedup vs baseline: 1.4340x; 1.4340x over previous
#include <cuda_runtime.h>
#include <stdint.h>

#define REP      640
#define ROWS     16
#define NBIN     64
#define MAXM     32768
#define MAXPAIR  8192

// -------- device-global scratch --------
__device__ unsigned g_ta[MAXM];            // a | b<<10 | w<<20
__device__ unsigned g_tc[MAXM];            // cg bits
__device__ int      g_tbp[MAXM];           // bin | pos<<6
__device__ __align__(16) unsigned g_prog[MAXPAIR * 4];
__device__ int g_npairs;
__device__ int g_split;                    // pair index splitting two halves
__device__ int g_irregular;

__device__ __forceinline__ unsigned smem_u32(const void* p) {
    unsigned a;
    asm("{ .reg .u64 t; cvta.to.shared.u64 t, %1; cvt.u32.u64 %0, t; }"
        : "=r"(a) : "l"(p));
    return a;
}

// ---- prep: runs -> 32-wide steps -> bin by 32-ch output block -> paired program
__global__ void k_prep(const void* __restrict__ r1, const void* __restrict__ r2,
                       const void* __restrict__ ro, const float* __restrict__ cg,
                       int M, int out_dim) {
    __shared__ unsigned char sflag[MAXM];
    __shared__ int scnt[NBIN], sbase[NBIN + 1], sdum[NBIN];
    __shared__ int s_ns;
    __shared__ unsigned s_or;
    int t = threadIdx.x;
    const unsigned* cgu = (const unsigned*)cg;

    if (t < NBIN) { scnt[t] = 0; sdum[t] = 0; }
    if (t == 0) { s_ns = 0; s_or = 0u; g_irregular = 0; }
    __syncthreads();

    // int64 detection: odd 32-bit words of ro all zero -> int64
    {
        const unsigned* rr = (const unsigned*)ro;
        int lim = (M < 4096) ? M : 4096;
        unsigned v = 0;
        for (int i = 1 + 2 * t; i < lim; i += 2048) v |= rr[i];
        if (v) s_or = 1u;              // benign race, same value
    }
    __syncthreads();
    int is64 = (s_or == 0u);
#define GETI(p, i) (is64 ? (int)((const long long*)(p))[i] : ((const int*)(p))[i])

    // run-break flags into smem
    for (int i = t; i < M; i += 1024) {
        int rb;
        if (i == 0) rb = 1;
        else rb = !((GETI(r1, i) == GETI(r1, i - 1) + 1) &&
                    (GETI(r2, i) == GETI(r2, i - 1) + 1) &&
                    (GETI(ro, i) == GETI(ro, i - 1) + 1) &&
                    (cgu[i] == cgu[i - 1]));
        sflag[i] = (unsigned char)rb;
    }
    __syncthreads();

    // run-start threads walk smem to find length; emit 32-wide steps
    for (int i = t; i < M; i += 1024) {
        if (!sflag[i]) continue;
        int j = i + 1;
        while (j < M && !sflag[j]) ++j;
        int L = j - i;
        int a0 = GETI(r1, i), b0 = GETI(r2, i), o0 = GETI(ro, i);
        unsigned cgv = cgu[i];
        if (o0 & 31) g_irregular = 1;                  // family guarantees aligned
        for (int k = 0; k < L; k += 32) {
            int w = (L - k < 32) ? (L - k) : 32;
            if (w < 32) g_irregular = 1;
            int bin = (o0 + k) >> 5;
            if (bin >= NBIN) { bin = NBIN - 1; g_irregular = 1; }
            int pos = atomicAdd(&scnt[bin], 1);
            int idx = atomicAdd(&s_ns, 1);
            if (idx < MAXM) {
                g_ta[idx]  = (unsigned)(a0 + k) | ((unsigned)(b0 + k) << 10)
                           | ((unsigned)w << 20);
                g_tc[idx]  = cgv;
                g_tbp[idx] = bin | (pos << 6);
            }
        }
    }
    __syncthreads();

    // pad bins to even; empty covered bins get one dummy pair (zero-fill flush)
    int nblk = (out_dim + 31) >> 5;
    if (nblk > NBIN) nblk = NBIN;
    if (t < NBIN) {
        if (t < nblk && scnt[t] == 0) { scnt[t] = 2; sdum[t] = 2; }
        else if (scnt[t] & 1)         { scnt[t] += 1; sdum[t] = 1; }
    }
    __syncthreads();

    if (t == 0) {
        int acc = 0;
        for (int b = 0; b < NBIN; ++b) { sbase[b] = acc; acc += scnt[b]; }
        sbase[NBIN] = acc;
        int Sp = acc >> 1;
        g_npairs = Sp;
        int half = Sp >> 1, best = 0, bd = 1 << 30;
        for (int b = 0; b <= NBIN; ++b) {
            int pb = sbase[b] >> 1;
            int d = pb - half; if (d < 0) d = -d;
            if (d < bd) { bd = d; best = pb; }
        }
        g_split = best;
    }
    __syncthreads();

    // scatter real steps into paired program words
    int ns = s_ns;
    if (ns > MAXM) ns = MAXM;
    for (int s = t; s < ns; s += 1024) {
        int bin = g_tbp[s] & 63, pos = g_tbp[s] >> 6;
        int slot = sbase[bin] + pos;
        int pr = slot >> 1;
        if (pr >= MAXPAIR) continue;
        unsigned ta = g_ta[s];
        if (slot & 1) {
            g_prog[pr * 4 + 2] = (ta & 0x03FFFFFFu) | ((unsigned)bin << 26);
            g_prog[pr * 4 + 3] = g_tc[s];
        } else {
            int lastpair = ((sbase[bin] + scnt[bin]) >> 1) - 1;
            unsigned fl = (pr == lastpair) ? 0x80000000u : 0u;
            g_prog[pr * 4 + 0] = (ta & 0x03FFFFFFu) | fl;
            g_prog[pr * 4 + 1] = g_tc[s];
        }
    }
    // dummy writes
    if (t < NBIN && sdum[t]) {
        if (sdum[t] == 2) {
            int pr = sbase[t] >> 1;
            g_prog[pr * 4 + 0] = 0x80000000u;
            g_prog[pr * 4 + 1] = 0u;
            g_prog[pr * 4 + 2] = (unsigned)t << 26;
            g_prog[pr * 4 + 3] = 0u;
        } else {
            int slot = sbase[t] + scnt[t] - 1;     // odd slot (base even)
            int pr = slot >> 1;
            g_prog[pr * 4 + 2] = (unsigned)t << 26;
            g_prog[pr * 4 + 3] = 0u;
        }
    }
#undef GETI
}

// ---- main: warp = batch row, 16 rows/CTA, 2 warps/row split the pair program
__global__ __launch_bounds__(1024, 2)
void k_main(const float* __restrict__ x1, const float* __restrict__ x2,
            float* __restrict__ out, int N, int out_dim) {
    extern __shared__ float xs[];            // [2][16][640] + mbar
    int tid  = threadIdx.x;
    int lane = tid & 31;
    int w    = tid >> 5;
    int row  = w & 15;
    int half = w >> 4;
    int rowbase = blockIdx.x * ROWS;

    unsigned mb = smem_u32(xs + 2 * ROWS * REP);

    if (rowbase + ROWS <= N) {
        if (tid == 0) {
            asm volatile("mbarrier.init.shared.b64 [%0], 1;" :: "r"(mb) : "memory");
        }
        __syncthreads();
        if (tid == 0) {
            unsigned d1 = smem_u32(xs);
            unsigned d2 = smem_u32(xs + ROWS * REP);
            const float* s1 = x1 + (size_t)rowbase * REP;
            const float* s2 = x2 + (size_t)rowbase * REP;
            asm volatile("mbarrier.arrive.expect_tx.shared.b64 _, [%0], %1;"
                         :: "r"(mb), "r"(2u * ROWS * REP * 4u) : "memory");
            asm volatile("cp.async.bulk.shared::cluster.global.mbarrier::complete_tx::bytes"
                         " [%0], [%1], %2, [%3];"
                         :: "r"(d1), "l"(s1), "r"(ROWS * REP * 4u), "r"(mb) : "memory");
            asm volatile("cp.async.bulk.shared::cluster.global.mbarrier::complete_tx::bytes"
                         " [%0], [%1], %2, [%3];"
                         :: "r"(d2), "l"(s2), "r"(ROWS * REP * 4u), "r"(mb) : "memory");
        }
        unsigned done = 0;
        while (!done)
            asm volatile("{ .reg .pred P; mbarrier.try_wait.parity.shared.b64 P, [%1], %2;"
                         " selp.b32 %0, 1, 0, P; }"
                         : "=r"(done) : "r"(mb), "r"(0u) : "memory");
    } else {
        for (int i = tid; i < ROWS * REP; i += 1024) {
            int gr = rowbase + i / REP;
            xs[i]              = (gr < N) ? x1[(size_t)gr * REP + (i % REP)] : 0.f;
            xs[ROWS * REP + i] = (gr < N) ? x2[(size_t)gr * REP + (i % REP)] : 0.f;
        }
        __syncthreads();
    }

    int gr = rowbase + row;
    if (gr >= N) return;

    int Sp    = g_npairs;
    int split = g_split;
    int lo = half ? split : 0;
    int hi = half ? Sp    : split;
    const float* p1 = xs + row * REP + lane;            // x1 row slice
    const float* p2 = p1 + ROWS * REP;                  // x2 via +imm offset
    const uint4* P  = (const uint4*)g_prog;
    float* orow = out + (size_t)gr * out_dim + lane;

    float acc = 0.f;
    if (!g_irregular) {
#pragma unroll 2
        for (int s = lo; s < hi; ++s) {
            uint4 st = P[s];                            // 2 entries, warp-uniform
            int a1 = st.x & 1023, b1 = (st.x >> 10) & 1023;
            int a2 = st.z & 1023, b2 = (st.z >> 10) & 1023;
            acc = fmaf(__uint_as_float(st.y) * p1[a1], p2[b1], acc);
            acc = fmaf(__uint_as_float(st.w) * p1[a2], p2[b2], acc);
            if ((int)st.x < 0) {                        // flush bit
                int o = (int)(st.z >> 26) << 5;
                if (o + lane < out_dim) orow[o] = acc;
                acc = 0.f;
            }
        }
    } else {
#pragma unroll 2
        for (int s = lo; s < hi; ++s) {
            uint4 st = P[s];
            int a1 = st.x & 1023, b1 = (st.x >> 10) & 1023;
            int a2 = st.z & 1023, b2 = (st.z >> 10) & 1023;
            float c1 = ((unsigned)lane < ((st.x >> 20) & 63u)) ? __uint_as_float(st.y) : 0.f;
            float c2 = ((unsigned)lane < ((st.z >> 20) & 63u)) ? __uint_as_float(st.w) : 0.f;
            acc = fmaf(c1 * p1[a1], p2[b1], acc);
            acc = fmaf(c2 * p1[a2], p2[b2], acc);
            if ((int)st.x < 0) {
                int o = (int)(st.z >> 26) << 5;
                if (o + lane < out_dim) orow[o] = acc;
                acc = 0.f;
            }
        }
    }
}

// -------- launcher --------
extern "C" void kernel_launch(void* const* d_in, const int* in_sizes, int n_in,
                              void* d_out, int out_size) {
    const float* x1 = (const float*)d_in[0];
    const float* x2 = (const float*)d_in[1];
    const float* cg = (const float*)d_in[2];
    const void*  r1 = d_in[3];
    const void*  r2 = d_in[4];
    const void*  ro = d_in[5];

    int M = in_sizes[2];
    if (M > MAXM) M = MAXM;
    int N = in_sizes[0] / REP;
    int out_dim = out_size / N;

    k_prep<<<1, 1024>>>(r1, r2, ro, cg, M, out_dim);

    int smem = 2 * ROWS * REP * (int)sizeof(float) + 16;   // tiles + mbarrier
    cudaFuncSetAttribute(k_main, cudaFuncAttributeMaxDynamicSharedMemorySize, smem);
    k_main<<<(N + ROWS - 1) / ROWS, 1024, smem>>>(x1, x2, (float*)d_out, N, out_dim);
}

// round 9
// speedup vs baseline: 1.6907x; 1.1790x over previous
#include <cuda_runtime.h>
#include <stdint.h>

#define REP      640
#define ROWS     16
#define NPAIR    8              // row pairs per CTA
#define NBIN     32             // 32-channel output bins (supports out_dim <= 1024)
#define MAXM     32768
#define MAXSTEP  1100           // M/32 max = 1024, + padding headroom
#define MAXPAIRS 600

// -------- device-global scratch --------
__device__ __align__(16) unsigned g_prog[MAXPAIRS * 4];
__device__ int g_q[5];          // quartile pair boundaries
__device__ int g_irregular;
__device__ int g_is64;
__device__ unsigned g_sab[MAXSTEP], g_scg[MAXSTEP];
__device__ int g_sbin[MAXSTEP], g_spos[MAXSTEP];

__device__ __forceinline__ int geti(const void* p, int i, int is64) {
    return is64 ? (int)((const long long*)p)[i] : ((const int*)p)[i];
}

// ---- prep: every 32-block is a step (verified); bin; pair; quartile split ----
__global__ void k_prep(const void* __restrict__ r1, const void* __restrict__ r2,
                       const void* __restrict__ ro, const float* __restrict__ cg,
                       int M, int out_dim) {
    __shared__ int scnt[NBIN], spad[NBIN], sdum[NBIN], sbase[NBIN + 1];
    __shared__ unsigned s_or;
    __shared__ int s_irr;
    int t = threadIdx.x;
    const unsigned* cgu = (const unsigned*)cg;

    if (t < NBIN) scnt[t] = 0;
    if (t == 0) { s_or = 0u; s_irr = (M & 31) ? 1 : 0; }
    __syncthreads();

    // int64 detect: odd 32-bit words of ro all zero -> int64
    {
        const unsigned* rr = (const unsigned*)ro;
        int lim = (M < 4096) ? M : 4096;
        unsigned v = 0;
        for (int i = 1 + 2 * t; i < lim; i += 2048) v |= rr[i];
        if (v) s_or = 1u;
    }
    __syncthreads();
    int is64 = (s_or == 0u);
    if (t == 0) g_is64 = is64;

    int S = M >> 5;
    // one parallel pass: continuation checks + direct step emit at i%32==0
    for (int i = t; i < M; i += 1024) {
        int a = geti(r1, i, is64), b = geti(r2, i, is64), o = geti(ro, i, is64);
        if (i & 31) {
            if (a != geti(r1, i - 1, is64) + 1 || b != geti(r2, i - 1, is64) + 1 ||
                o != geti(ro, i - 1, is64) + 1 || cgu[i] != cgu[i - 1])
                s_irr = 1;
        } else {
            int s = i >> 5;
            int bin = o >> 5;
            if ((o & 31) || (unsigned)a > 1023u - 31u || (unsigned)b > 1023u - 31u ||
                (unsigned)bin >= NBIN) {
                s_irr = 1; a = 0; b = 0; bin = 0;
            }
            if (s < MAXSTEP) {
                g_sab[s]  = (unsigned)a | ((unsigned)b << 10);
                g_scg[s]  = cgu[i];
                g_sbin[s] = bin;
                g_spos[s] = atomicAdd(&scnt[bin], 1);
            }
        }
    }
    __syncthreads();

    // pad bins to even; covered empty bins get a dummy pair (zero-fill via flush)
    int nblk = (out_dim + 31) >> 5;
    if (nblk > NBIN) nblk = NBIN;
    if (t < NBIN) {
        int c = scnt[t], d = 0;
        if (t < nblk && c == 0) { c = 2; d = 2; }
        else if (c & 1)         { c += 1; d = 1; }
        spad[t] = c; sdum[t] = d;
    }
    __syncthreads();

    // warp-0 inclusive shuffle scan over 32 bins
    if (t < 32) {
        int v = spad[t], inc = v;
        for (int off = 1; off < 32; off <<= 1) {
            int u = __shfl_up_sync(0xffffffffu, inc, off);
            if (t >= off) inc += u;
        }
        sbase[t] = inc - v;
        if (t == 31) sbase[32] = inc;
    }
    __syncthreads();

    int Sp = sbase[NBIN] >> 1;
    if (t == 0) {
        g_irregular = s_irr;
        g_q[0] = 0; g_q[4] = Sp;
        for (int k = 1; k < 4; ++k) {
            int target = (Sp * k) >> 2, best = 0, bd = 1 << 30;
            for (int b = 0; b <= NBIN; ++b) {
                int pb = sbase[b] >> 1;
                int d = pb - target; if (d < 0) d = -d;
                if (d < bd) { bd = d; best = pb; }
            }
            g_q[k] = best;
        }
    }
    __syncthreads();

    // scatter steps into paired program
    for (int s = t; s < S && s < MAXSTEP; s += 1024) {
        int bin = g_sbin[s];
        int slot = sbase[bin] + g_spos[s];
        int pr = slot >> 1;
        if (pr >= MAXPAIRS) continue;
        unsigned ab = g_sab[s] & 0x000FFFFFu;
        if (slot & 1) {
            g_prog[pr * 4 + 2] = ab | ((unsigned)bin << 26);
            g_prog[pr * 4 + 3] = g_scg[s];
        } else {
            int lastpair = ((sbase[bin] + spad[bin]) >> 1) - 1;
            g_prog[pr * 4 + 0] = ab | ((pr == lastpair) ? 0x80000000u : 0u);
            g_prog[pr * 4 + 1] = g_scg[s];
        }
    }
    if (t < NBIN && sdum[t]) {
        if (sdum[t] == 2) {
            int pr = sbase[t] >> 1;
            if (pr < MAXPAIRS) {
                g_prog[pr * 4 + 0] = 0x80000000u;
                g_prog[pr * 4 + 1] = 0u;
                g_prog[pr * 4 + 2] = (unsigned)t << 26;
                g_prog[pr * 4 + 3] = 0u;
            }
        } else {
            int pr = (sbase[t] + spad[t] - 1) >> 1;
            if (pr < MAXPAIRS) {
                g_prog[pr * 4 + 2] = (unsigned)t << 26;
                g_prog[pr * 4 + 3] = 0u;
            }
        }
    }
}

// ---- main: warp = row pair, packed f32x2; 8 pairs x 4 program quarters ----
__global__ __launch_bounds__(1024, 2)
void k_main(const float* __restrict__ x1, const float* __restrict__ x2,
            float* __restrict__ out, int N, int out_dim,
            const void* __restrict__ r1, const void* __restrict__ r2,
            const void* __restrict__ ro, const float* __restrict__ cg, int M) {
    extern __shared__ unsigned long long smu[];
    int tid  = threadIdx.x;
    int lane = tid & 31;
    int w    = tid >> 5;
    int rowbase = blockIdx.x * ROWS;

    if (!g_irregular) {
        unsigned long long* xs1 = smu;                   // [8][640] {row2p,row2p+1}
        unsigned long long* xs2 = smu + NPAIR * REP;

        if (rowbase + ROWS <= N) {
            for (int i = tid; i < NPAIR * (REP / 2); i += 1024) {
                int p = i / (REP / 2);
                int c = (i - p * (REP / 2)) * 2;
                const float* a0p = x1 + (size_t)(rowbase + 2 * p) * REP + c;
                const float* b0p = x2 + (size_t)(rowbase + 2 * p) * REP + c;
                float2 a0 = *(const float2*)a0p;
                float2 a1 = *(const float2*)(a0p + REP);
                float2 b0 = *(const float2*)b0p;
                float2 b1 = *(const float2*)(b0p + REP);
                xs1[p * REP + c]     = (unsigned long long)__float_as_uint(a0.x)
                                     | ((unsigned long long)__float_as_uint(a1.x) << 32);
                xs1[p * REP + c + 1] = (unsigned long long)__float_as_uint(a0.y)
                                     | ((unsigned long long)__float_as_uint(a1.y) << 32);
                xs2[p * REP + c]     = (unsigned long long)__float_as_uint(b0.x)
                                     | ((unsigned long long)__float_as_uint(b1.x) << 32);
                xs2[p * REP + c + 1] = (unsigned long long)__float_as_uint(b0.y)
                                     | ((unsigned long long)__float_as_uint(b1.y) << 32);
            }
        } else {
            for (int i = tid; i < NPAIR * REP; i += 1024) {
                int p = i / REP, c = i - p * REP;
                int ga = rowbase + 2 * p, gb = ga + 1;
                float a0 = (ga < N) ? x1[(size_t)ga * REP + c] : 0.f;
                float a1 = (gb < N) ? x1[(size_t)gb * REP + c] : 0.f;
                float b0 = (ga < N) ? x2[(size_t)ga * REP + c] : 0.f;
                float b1 = (gb < N) ? x2[(size_t)gb * REP + c] : 0.f;
                xs1[i] = (unsigned long long)__float_as_uint(a0)
                       | ((unsigned long long)__float_as_uint(a1) << 32);
                xs2[i] = (unsigned long long)__float_as_uint(b0)
                       | ((unsigned long long)__float_as_uint(b1) << 32);
            }
        }
        __syncthreads();

        int pairi = w & (NPAIR - 1);
        int q     = w >> 3;
        int lo = g_q[q], hi = g_q[q + 1];
        const unsigned long long* bp1 = xs1 + pairi * REP + lane;
        const unsigned long long* bp2 = xs2 + pairi * REP + lane;
        const uint4* P = (const uint4*)g_prog;
        int gr0 = rowbase + 2 * pairi, gr1 = gr0 + 1;
        float* o0 = out + (size_t)gr0 * out_dim + lane;
        float* o1 = out + (size_t)gr1 * out_dim + lane;

        unsigned long long acc = 0ull;
#pragma unroll 2
        for (int s = lo; s < hi; ++s) {
            uint4 st = P[s];
            {
                unsigned long long va = bp1[st.x & 1023u];
                unsigned long long vb = bp2[(st.x >> 10) & 1023u];
                unsigned long long cg2 = ((unsigned long long)st.y << 32) | st.y;
                unsigned long long m;
                asm("mul.rn.f32x2 %0, %1, %2;" : "=l"(m) : "l"(va), "l"(vb));
                asm("fma.rn.f32x2 %0, %1, %2, %3;" : "=l"(acc) : "l"(m), "l"(cg2), "l"(acc));
            }
            {
                unsigned long long va = bp1[st.z & 1023u];
                unsigned long long vb = bp2[(st.z >> 10) & 1023u];
                unsigned long long cg2 = ((unsigned long long)st.w << 32) | st.w;
                unsigned long long m;
                asm("mul.rn.f32x2 %0, %1, %2;" : "=l"(m) : "l"(va), "l"(vb));
                asm("fma.rn.f32x2 %0, %1, %2, %3;" : "=l"(acc) : "l"(m), "l"(cg2), "l"(acc));
            }
            if ((int)st.x < 0) {                           // flush bit
                int o = (int)((st.z >> 26) & 63u) << 5;
                if (o + lane < out_dim) {
                    if (gr0 < N) o0[o] = __uint_as_float((unsigned)acc);
                    if (gr1 < N) o1[o] = __uint_as_float((unsigned)(acc >> 32));
                }
                acc = 0ull;
            }
        }
    } else {
        // -------- correct-but-slow fallback (never taken for this generator) ----
        float* f1 = (float*)smu;                 // [16][640]
        float* f2 = f1 + ROWS * REP;
        for (int i = tid; i < ROWS * REP; i += 1024) {
            int r = i / REP, c = i - r * REP;
            int gr = rowbase + r;
            f1[i] = (gr < N) ? x1[(size_t)gr * REP + c] : 0.f;
            f2[i] = (gr < N) ? x2[(size_t)gr * REP + c] : 0.f;
        }
        for (int i = tid; i < ROWS * out_dim; i += 1024) {
            int gr = rowbase + i / out_dim;
            if (gr < N) out[(size_t)gr * out_dim + (i % out_dim)] = 0.f;
        }
        __syncthreads();
        int is64 = g_is64;
        for (int e = tid; e < M; e += 1024) {
            int a = geti(r1, e, is64), b = geti(r2, e, is64), o = geti(ro, e, is64);
            float c = cg[e];
            if ((unsigned)a >= (unsigned)REP || (unsigned)b >= (unsigned)REP ||
                (unsigned)o >= (unsigned)out_dim) continue;
            for (int r = 0; r < ROWS; ++r) {
                int gr = rowbase + r;
                if (gr < N)
                    atomicAdd(&out[(size_t)gr * out_dim + o],
                              c * f1[r * REP + a] * f2[r * REP + b]);
            }
        }
    }
}

// -------- launcher --------
extern "C" void kernel_launch(void* const* d_in, const int* in_sizes, int n_in,
                              void* d_out, int out_size) {
    const float* x1 = (const float*)d_in[0];
    const float* x2 = (const float*)d_in[1];
    const float* cg = (const float*)d_in[2];
    const void*  r1 = d_in[3];
    const void*  r2 = d_in[4];
    const void*  ro = d_in[5];

    int M = in_sizes[2];
    if (M > MAXM) M = MAXM;
    int N = in_sizes[0] / REP;
    int out_dim = out_size / N;

    k_prep<<<1, 1024>>>(r1, r2, ro, cg, M, out_dim);

    int smem = 2 * NPAIR * REP * (int)sizeof(unsigned long long);   // 81920
    cudaFuncSetAttribute(k_main, cudaFuncAttributeMaxDynamicSharedMemorySize, smem);
    k_main<<<(N + ROWS - 1) / ROWS, 1024, smem>>>(x1, x2, (float*)d_out,
                                                  N, out_dim, r1, r2, ro, cg, M);
}

// round 11
// speedup vs baseline: 1.8153x; 1.0737x over previous
#include <cuda_runtime.h>
#include <stdint.h>

#define REP      640
#define ROWS     16
#define NQUAD    4              // row quads per CTA
#define NSEG     8              // program octiles (one per warp group)
#define NBIN     32             // 32-channel output bins (out_dim <= 1024)
#define MAXM     32768
#define MAXSTEP  1024           // M/32
#define MAXPROG  (MAXSTEP + NBIN)

// -------- device-global scratch --------
__device__ __align__(8) uint2 g_prog[MAXPROG];   // {a|b<<10|bin<<20|flush<<31, cg}
__device__ int g_q[NSEG + 1];                    // octile entry boundaries
__device__ int g_irregular;
__device__ int g_is64;

__device__ __forceinline__ int geti(const void* p, int i, int is64) {
    return is64 ? (int)((const long long*)p)[i] : ((const int*)p)[i];
}

// ---- prep: every 32-block is a step (verified); bin; octile split ----
__global__ void k_prep(const void* __restrict__ r1, const void* __restrict__ r2,
                       const void* __restrict__ ro, const float* __restrict__ cg,
                       int M, int out_dim) {
    __shared__ unsigned sab[MAXSTEP], scgv[MAXSTEP];
    __shared__ unsigned short sbin[MAXSTEP], spos[MAXSTEP];
    __shared__ int scnt[NBIN], sdum[NBIN], sbase[NBIN + 1];
    __shared__ unsigned s_or;
    __shared__ int s_irr;
    int t = threadIdx.x;
    const unsigned* cgu = (const unsigned*)cg;

    if (t < NBIN) { scnt[t] = 0; sdum[t] = 0; }
    if (t == 0) { s_or = 0u; s_irr = ((M & 31) || M > MAXM) ? 1 : 0; }
    __syncthreads();
    int Mc = (M > MAXM) ? MAXM : M;

    // int64 detect: odd 32-bit words of ro all zero -> int64
    {
        const unsigned* rr = (const unsigned*)ro;
        int lim = (Mc < 4096) ? Mc : 4096;
        unsigned v = 0;
        for (int i = 1 + 2 * t; i < lim; i += 2048) v |= rr[i];
        if (v) s_or = 1u;
    }
    __syncthreads();
    int is64 = (s_or == 0u);
    if (t == 0) g_is64 = is64;

    int S = Mc >> 5;
    // one pass: continuation verify + step emit at i%32==0
    for (int i = t; i < Mc; i += 1024) {
        int a = geti(r1, i, is64), b = geti(r2, i, is64), o = geti(ro, i, is64);
        if (i & 31) {
            if (a != geti(r1, i - 1, is64) + 1 || b != geti(r2, i - 1, is64) + 1 ||
                o != geti(ro, i - 1, is64) + 1 || cgu[i] != cgu[i - 1])
                s_irr = 1;
        } else {
            int s = i >> 5;
            int bin = o >> 5;
            if ((o & 31) || (unsigned)a > (unsigned)(REP - 32) ||
                (unsigned)b > (unsigned)(REP - 32) || (unsigned)bin >= NBIN) {
                s_irr = 1; a = 0; b = 0; bin = 0;
            }
            sab[s]  = (unsigned)a | ((unsigned)b << 10);
            scgv[s] = cgu[i];
            sbin[s] = (unsigned short)bin;
            spos[s] = (unsigned short)atomicAdd(&scnt[bin], 1);
        }
    }
    __syncthreads();

    // covered empty bins get one dummy entry (zero-fill via flush of acc=0)
    int nblk = (out_dim + 31) >> 5;
    if (nblk > NBIN) nblk = NBIN;
    if (t < NBIN && t < nblk && scnt[t] == 0) { scnt[t] = 1; sdum[t] = 1; }
    __syncthreads();

    // warp-0 shuffle scan over 32 bins
    if (t < 32) {
        int v = scnt[t], inc = v;
        for (int off = 1; off < 32; off <<= 1) {
            int u = __shfl_up_sync(0xffffffffu, inc, off);
            if (t >= off) inc += u;
        }
        sbase[t] = inc - v;
        if (t == 31) sbase[32] = inc;
    }
    __syncthreads();

    int Sp = sbase[NBIN];
    if (t == 0) {
        g_irregular = s_irr;
        g_q[0] = 0; g_q[NSEG] = Sp;
        for (int k = 1; k < NSEG; ++k) {
            int target = (Sp * k) / NSEG, best = 0, bd = 1 << 30;
            for (int b = 0; b <= NBIN; ++b) {
                int d = sbase[b] - target; if (d < 0) d = -d;
                if (d < bd) { bd = d; best = sbase[b]; }
            }
            g_q[k] = best;
        }
    }
    __syncthreads();

    // scatter steps to global program; flush on last slot of each bin
    for (int s = t; s < S; s += 1024) {
        int bin = sbin[s];
        int slot = sbase[bin] + spos[s];
        unsigned fl = (slot == sbase[bin + 1] - 1) ? 0x80000000u : 0u;
        g_prog[slot] = make_uint2(sab[s] | ((unsigned)bin << 20) | fl, scgv[s]);
    }
    if (t < NBIN && sdum[t])
        g_prog[sbase[t]] = make_uint2(((unsigned)t << 20) | 0x80000000u, 0u);
}

// ---- main: warp = row quad (float4/chan, LDS.128), 4 quads x 8 octiles ----
__global__ __launch_bounds__(1024, 2)
void k_main(const float* __restrict__ x1, const float* __restrict__ x2,
            float* __restrict__ out, int N, int out_dim,
            const void* __restrict__ r1, const void* __restrict__ r2,
            const void* __restrict__ ro, const float* __restrict__ cg, int M) {
    extern __shared__ float4 smq[];                 // [2][NQUAD][REP] quad-packed
    int tid  = threadIdx.x;
    int lane = tid & 31;
    int w    = tid >> 5;
    int rowbase = blockIdx.x * ROWS;

    if (!g_irregular) {
        float4* xs1 = smq;
        float4* xs2 = smq + NQUAD * REP;

        if (rowbase + ROWS <= N) {
            for (int i = tid; i < NQUAD * REP; i += 1024) {
                int q = i / REP, c = i - q * REP;
                const float* base1 = x1 + (size_t)(rowbase + 4 * q) * REP + c;
                const float* base2 = x2 + (size_t)(rowbase + 4 * q) * REP + c;
                xs1[i] = make_float4(base1[0], base1[REP], base1[2 * REP], base1[3 * REP]);
                xs2[i] = make_float4(base2[0], base2[REP], base2[2 * REP], base2[3 * REP]);
            }
        } else {
            for (int i = tid; i < NQUAD * REP; i += 1024) {
                int q = i / REP, c = i - q * REP;
                float v1[4], v2[4];
#pragma unroll
                for (int k = 0; k < 4; ++k) {
                    int gr = rowbase + 4 * q + k;
                    v1[k] = (gr < N) ? x1[(size_t)gr * REP + c] : 0.f;
                    v2[k] = (gr < N) ? x2[(size_t)gr * REP + c] : 0.f;
                }
                xs1[i] = make_float4(v1[0], v1[1], v1[2], v1[3]);
                xs2[i] = make_float4(v2[0], v2[1], v2[2], v2[3]);
            }
        }
        __syncthreads();

        int quad = w & (NQUAD - 1);
        int seg  = w >> 2;
        int lo = g_q[seg], hi = g_q[seg + 1];
        const ulonglong2* p1 = (const ulonglong2*)smq + quad * REP + lane;
        const ulonglong2* p2 = p1 + NQUAD * REP;
        const uint2* P = (const uint2*)g_prog;
        int gr0 = rowbase + 4 * quad;
        float* ob = out + (size_t)gr0 * out_dim + lane;

        unsigned long long acc0 = 0ull, acc1 = 0ull;
#pragma unroll 4
        for (int s = lo; s < hi; ++s) {
            uint2 st = P[s];                                   // warp-uniform
            unsigned ax = st.x;
            ulonglong2 va = p1[ax & 1023u];
            ulonglong2 vb = p2[(ax >> 10) & 1023u];
            unsigned long long cg2 = ((unsigned long long)st.y << 32) | st.y;
            unsigned long long m0, m1;
            asm("mul.rn.f32x2 %0, %1, %2;" : "=l"(m0) : "l"(va.x), "l"(vb.x));
            asm("fma.rn.f32x2 %0, %1, %2, %3;" : "=l"(acc0) : "l"(m0), "l"(cg2), "l"(acc0));
            asm("mul.rn.f32x2 %0, %1, %2;" : "=l"(m1) : "l"(va.y), "l"(vb.y));
            asm("fma.rn.f32x2 %0, %1, %2, %3;" : "=l"(acc1) : "l"(m1), "l"(cg2), "l"(acc1));
            if ((int)ax < 0) {                                 // flush bit
                int o = (int)((ax >> 20) & 63u) << 5;
                if (o + lane < out_dim) {
                    float* op = ob + o;
                    if (gr0 + 0 < N) op[0]               = __uint_as_float((unsigned)acc0);
                    if (gr0 + 1 < N) op[(size_t)out_dim] = __uint_as_float((unsigned)(acc0 >> 32));
                    if (gr0 + 2 < N) op[2 * (size_t)out_dim] = __uint_as_float((unsigned)acc1);
                    if (gr0 + 3 < N) op[3 * (size_t)out_dim] = __uint_as_float((unsigned)(acc1 >> 32));
                }
                acc0 = 0ull; acc1 = 0ull;
            }
        }
    } else {
        // -------- correct-but-slow fallback (never taken for this generator) ----
        float* f1 = (float*)smq;                 // [16][640]
        float* f2 = f1 + ROWS * REP;
        for (int i = tid; i < ROWS * REP; i += 1024) {
            int r = i / REP, c = i - r * REP;
            int gr = rowbase + r;
            f1[i] = (gr < N) ? x1[(size_t)gr * REP + c] : 0.f;
            f2[i] = (gr < N) ? x2[(size_t)gr * REP + c] : 0.f;
        }
        for (int i = tid; i < ROWS * out_dim; i += 1024) {
            int gr = rowbase + i / out_dim;
            if (gr < N) out[(size_t)gr * out_dim + (i % out_dim)] = 0.f;
        }
        __syncthreads();
        int is64 = g_is64;
        for (int e = tid; e < M; e += 1024) {
            int a = geti(r1, e, is64), b = geti(r2, e, is64), o = geti(ro, e, is64);
            float c = cg[e];
            if ((unsigned)a >= (unsigned)REP || (unsigned)b >= (unsigned)REP ||
                (unsigned)o >= (unsigned)out_dim) continue;
            for (int r = 0; r < ROWS; ++r) {
                int gr = rowbase + r;
                if (gr < N)
                    atomicAdd(&out[(size_t)gr * out_dim + o],
                              c * f1[r * REP + a] * f2[r * REP + b]);
            }
        }
    }
}

// -------- launcher --------
extern "C" void kernel_launch(void* const* d_in, const int* in_sizes, int n_in,
                              void* d_out, int out_size) {
    const float* x1 = (const float*)d_in[0];
    const float* x2 = (const float*)d_in[1];
    const float* cg = (const float*)d_in[2];
    const void*  r1 = d_in[3];
    const void*  r2 = d_in[4];
    const void*  ro = d_in[5];

    int M = in_sizes[2];
    int N = in_sizes[0] / REP;
    int out_dim = out_size / N;

    k_prep<<<1, 1024>>>(r1, r2, ro, cg, M, out_dim);

    int smem = 2 * NQUAD * REP * (int)sizeof(float4);   // 81920
    cudaFuncSetAttribute(k_main, cudaFuncAttributeMaxDynamicSharedMemorySize, smem);
    k_main<<<(N + ROWS - 1) / ROWS, 1024, smem>>>(x1, x2, (float*)d_out,
                                                  N, out_dim, r1, r2, ro, cg, M);
}